// round 14
// baseline (speedup 1.0000x reference)
#include <cuda_runtime.h>

// 2-layer LSTM (IN=16, H=32, T=512, B=4096) + MLP head, fully fused.
// R14 = R13 (layer-split warp pairs, S=8, smem-staged seq-pair acts, HW
// tanh.approx activations) + CROSS-PAIR SMSP ASSIGNMENT:
//   L0 of pair p  -> warp p     (SMSP p)
//   L1 of pair p  -> warp 4 + ((p-1)&3)  i.e. L1 warp w serves pair (w&3+1)&3
// Each SMSP still hosts exactly one L0 + one L1 warp (FMA balanced), but the
// two warps belong to DIFFERENT pairs with independent barriers -- when one
// pair stalls at its handoff bar, the SMSP's other warp keeps issuing.
// R13 had both warps of a pair on one SMSP: every bar idled that SMSP.

#define FULLMASK 0xffffffffu
typedef unsigned long long u64;

constexpr int T_LEN = 512;
constexpr int IN_DIM = 16;
constexpr int H_DIM = 32;
constexpr int SEQ_PER_PAIR = 8;
constexpr int PAIRS_PER_BLOCK = 4;
constexpr int THREADS = 256;
constexpr int HROW = 34;              // u64 row stride (272B, 16B-aligned)
constexpr int XROW = 18;              // u64 row stride (144B, 16B-aligned)

// Weights: [j][unit] float4 = (wi,wf,wg,wo).
struct SmemW {
    float4 wih0[IN_DIM][H_DIM];
    float4 whh0[H_DIM][H_DIM];
    float4 wih1[H_DIM][H_DIM];
    float4 whh1[H_DIM][H_DIM];
    float4 bg0[H_DIM];
    float4 bg1[H_DIM];
};

// Per-pair staging. Rows: [seq-pair sp][unit/dim as u64 = (val_s0, val_s1)]
struct __align__(16) Stage {
    u64 h0[2][4][HROW];   // double-buffered, written by L0, read by both
    u64 h1[2][4][HROW];   // L1-private
    u64 x[2][4][XROW];    // L0-private
};

struct SmemAll {
    SmemW w;
    Stage st[PAIRS_PER_BLOCK];
};

__device__ __forceinline__ u64 fma2(u64 a, u64 b, u64 c) {
    u64 d;
    asm("fma.rn.f32x2 %0, %1, %2, %3;" : "=l"(d) : "l"(a), "l"(b), "l"(c));
    return d;
}
__device__ __forceinline__ u64 pack2(float v) {
    u64 r;
    asm("mov.b64 %0, {%1, %1};" : "=l"(r) : "f"(v));
    return r;
}
__device__ __forceinline__ u64 pack2f(float a, float b) {
    u64 r;
    asm("mov.b64 %0, {%1, %2};" : "=l"(r) : "f"(a), "f"(b));
    return r;
}
__device__ __forceinline__ float2 unpack2(u64 v) {
    float2 r;
    asm("mov.b64 {%0, %1}, %2;" : "=f"(r.x), "=f"(r.y) : "l"(v));
    return r;
}

__device__ __forceinline__ float tanh_ap(float v) {
    float r;
    asm("tanh.approx.f32 %0, %1;" : "=f"(r) : "f"(v));
    return r;
}
__device__ __forceinline__ float sig_ap(float v) {
    return fmaf(tanh_ap(v * 0.5f), 0.5f, 0.5f);
}

__device__ __forceinline__ void pair_bar(int pair) {
    asm volatile("bar.sync %0, %1;" :: "r"(pair + 1), "r"(64) : "memory");
}

// One j-pair contribution: weight quads w0 (j=2jp), w1 (j=2jp+1); acts are
// seq-pair-packed u64. 8 FFMA2 per sp.
#define JP_STEP(W0, W1, ACTP)                                              \
    do {                                                                   \
        u64 wi0 = pack2((W0).x), wf0 = pack2((W0).y);                      \
        u64 wg0 = pack2((W0).z), wo0 = pack2((W0).w);                      \
        u64 wi1 = pack2((W1).x), wf1 = pack2((W1).y);                      \
        u64 wg1 = pack2((W1).z), wo1 = pack2((W1).w);                      \
        _Pragma("unroll")                                                  \
        for (int sp = 0; sp < 4; sp++) {                                   \
            ulonglong2 a = *reinterpret_cast<const ulonglong2*>(ACTP(sp)); \
            ai[sp] = fma2(wi0, a.x, ai[sp]);                               \
            af[sp] = fma2(wf0, a.x, af[sp]);                               \
            ag[sp] = fma2(wg0, a.x, ag[sp]);                               \
            ao[sp] = fma2(wo0, a.x, ao[sp]);                               \
            ai[sp] = fma2(wi1, a.y, ai[sp]);                               \
            af[sp] = fma2(wf1, a.y, af[sp]);                               \
            ag[sp] = fma2(wg1, a.y, ag[sp]);                               \
            ao[sp] = fma2(wo1, a.y, ao[sp]);                               \
        }                                                                  \
    } while (0)

__global__ void __launch_bounds__(THREADS, 1)
lstm_fused_kernel(const float* __restrict__ x,
                  const float* __restrict__ Wih0, const float* __restrict__ Whh0,
                  const float* __restrict__ bih0, const float* __restrict__ bhh0,
                  const float* __restrict__ Wih1, const float* __restrict__ Whh1,
                  const float* __restrict__ bih1, const float* __restrict__ bhh1,
                  const float* __restrict__ W1, const float* __restrict__ b1,
                  const float* __restrict__ W2, const float* __restrict__ b2,
                  float* __restrict__ out, int batch) {
    extern __shared__ char smem_raw[];
    SmemAll* sm = reinterpret_cast<SmemAll*>(smem_raw);
    SmemW* s = &sm->w;

    const int tid = threadIdx.x;

    // ---- Stage weights as [j][unit] gate quads ----
    for (int i = tid; i < IN_DIM * H_DIM; i += THREADS) {
        int j = i / H_DIM, u = i % H_DIM;
        s->wih0[j][u] = make_float4(Wih0[(0 * H_DIM + u) * IN_DIM + j],
                                    Wih0[(1 * H_DIM + u) * IN_DIM + j],
                                    Wih0[(2 * H_DIM + u) * IN_DIM + j],
                                    Wih0[(3 * H_DIM + u) * IN_DIM + j]);
    }
    for (int i = tid; i < H_DIM * H_DIM; i += THREADS) {
        int j = i / H_DIM, u = i % H_DIM;
        s->whh0[j][u] = make_float4(Whh0[(0 * H_DIM + u) * H_DIM + j],
                                    Whh0[(1 * H_DIM + u) * H_DIM + j],
                                    Whh0[(2 * H_DIM + u) * H_DIM + j],
                                    Whh0[(3 * H_DIM + u) * H_DIM + j]);
        s->wih1[j][u] = make_float4(Wih1[(0 * H_DIM + u) * H_DIM + j],
                                    Wih1[(1 * H_DIM + u) * H_DIM + j],
                                    Wih1[(2 * H_DIM + u) * H_DIM + j],
                                    Wih1[(3 * H_DIM + u) * H_DIM + j]);
        s->whh1[j][u] = make_float4(Whh1[(0 * H_DIM + u) * H_DIM + j],
                                    Whh1[(1 * H_DIM + u) * H_DIM + j],
                                    Whh1[(2 * H_DIM + u) * H_DIM + j],
                                    Whh1[(3 * H_DIM + u) * H_DIM + j]);
    }
    for (int u = tid; u < H_DIM; u += THREADS) {
        s->bg0[u] = make_float4(bih0[0 * H_DIM + u] + bhh0[0 * H_DIM + u],
                                bih0[1 * H_DIM + u] + bhh0[1 * H_DIM + u],
                                bih0[2 * H_DIM + u] + bhh0[2 * H_DIM + u],
                                bih0[3 * H_DIM + u] + bhh0[3 * H_DIM + u]);
        s->bg1[u] = make_float4(bih1[0 * H_DIM + u] + bhh1[0 * H_DIM + u],
                                bih1[1 * H_DIM + u] + bhh1[1 * H_DIM + u],
                                bih1[2 * H_DIM + u] + bhh1[2 * H_DIM + u],
                                bih1[3 * H_DIM + u] + bhh1[3 * H_DIM + u]);
    }

    const int warp = tid >> 5;
    const int lane = tid & 31;         // lane = hidden unit
    const int wq = warp & 3;           // SMSP index
    const int role = warp >> 2;        // 0 = layer-0 warp, 1 = layer-1 warp
    // Cross-pair assignment: L1 warp on SMSP q serves pair (q+1)&3, so the
    // two warps of a pair sit on DIFFERENT SMSPs.
    const int pair = (role == 0) ? wq : ((wq + 1) & 3);
    Stage* st = &sm->st[pair];
    const int seq_base = (blockIdx.x * PAIRS_PER_BLOCK + pair) * SEQ_PER_PAIR;

    const int xs = lane >> 2;
    const int xq = lane & 3;
    const size_t seq_stride = (size_t)T_LEN * IN_DIM;
    const float* xload = x + (size_t)(seq_base + xs) * seq_stride + 4 * xq;

    // ---- Init staging ----
    if (seq_base < batch) {
        if (role == 0) {
#pragma unroll
            for (int sp = 0; sp < 4; sp++) st->h0[0][sp][lane] = 0ull;
            float4 v = *reinterpret_cast<const float4*>(xload);
            float* fr = reinterpret_cast<float*>(st->x[0][xs >> 1]);
            int half = xs & 1;
            fr[(4 * xq + 0) * 2 + half] = v.x;
            fr[(4 * xq + 1) * 2 + half] = v.y;
            fr[(4 * xq + 2) * 2 + half] = v.z;
            fr[(4 * xq + 3) * 2 + half] = v.w;
        } else {
#pragma unroll
            for (int sp = 0; sp < 4; sp++) st->h1[0][sp][lane] = 0ull;
        }
    }
    __syncthreads();
    if (seq_base >= batch) return;

    if (role == 0) {
        // ================= Layer-0 warp =================
        const float4 bv = s->bg0[lane];
        const u64 BI = pack2(bv.x), BF = pack2(bv.y);
        const u64 BG = pack2(bv.z), BO = pack2(bv.w);
        float c0[8] = {0, 0, 0, 0, 0, 0, 0, 0};

        for (int t = 0; t < T_LEN; t++) {
            const int buf = t & 1, nbuf = buf ^ 1;
            float4 xn = make_float4(0.f, 0.f, 0.f, 0.f);
            if (t + 1 < T_LEN)
                xn = *reinterpret_cast<const float4*>(xload + (t + 1) * IN_DIM);

            u64 ai[4], af[4], ag[4], ao[4];
#pragma unroll
            for (int sp = 0; sp < 4; sp++) {
                ai[sp] = BI; af[sp] = BF; ag[sp] = BG; ao[sp] = BO;
            }
#pragma unroll
            for (int jp = 0; jp < IN_DIM / 2; jp++) {
                float4 w0 = s->wih0[2 * jp][lane];
                float4 w1 = s->wih0[2 * jp + 1][lane];
#define ACT_X(sp) (&st->x[buf][sp][2 * jp])
                JP_STEP(w0, w1, ACT_X);
#undef ACT_X
            }
#pragma unroll
            for (int jp = 0; jp < H_DIM / 2; jp++) {
                float4 w0 = s->whh0[2 * jp][lane];
                float4 w1 = s->whh0[2 * jp + 1][lane];
#define ACT_H0(sp) (&st->h0[buf][sp][2 * jp])
                JP_STEP(w0, w1, ACT_H0);
#undef ACT_H0
            }
            // Cell 0 + stage h0(t)
#pragma unroll
            for (int sp = 0; sp < 4; sp++) {
                float2 vi = unpack2(ai[sp]), vf = unpack2(af[sp]);
                float2 vg = unpack2(ag[sp]), vo = unpack2(ao[sp]);
                float i0 = sig_ap(vi.x), i1 = sig_ap(vi.y);
                float f0 = sig_ap(vf.x), f1 = sig_ap(vf.y);
                float g0 = tanh_ap(vg.x), g1 = tanh_ap(vg.y);
                float o0 = sig_ap(vo.x), o1 = sig_ap(vo.y);
                c0[2 * sp]     = fmaf(f0, c0[2 * sp],     i0 * g0);
                c0[2 * sp + 1] = fmaf(f1, c0[2 * sp + 1], i1 * g1);
                st->h0[nbuf][sp][lane] =
                    pack2f(o0 * tanh_ap(c0[2 * sp]),
                           o1 * tanh_ap(c0[2 * sp + 1]));
            }
            // Stage x(t+1)
            {
                float* fr = reinterpret_cast<float*>(st->x[nbuf][xs >> 1]);
                int half = xs & 1;
                fr[(4 * xq + 0) * 2 + half] = xn.x;
                fr[(4 * xq + 1) * 2 + half] = xn.y;
                fr[(4 * xq + 2) * 2 + half] = xn.z;
                fr[(4 * xq + 3) * 2 + half] = xn.w;
            }
            pair_bar(pair);  // h0(t) + x(t+1) visible to the L1 warp
        }
        return;
    }

    // ================= Layer-1 warp =================
    const float4 bv = s->bg1[lane];
    const u64 BI = pack2(bv.x), BF = pack2(bv.y);
    const u64 BG = pack2(bv.z), BO = pack2(bv.w);
    float c1[8] = {0, 0, 0, 0, 0, 0, 0, 0};
    float h1n[8] = {0, 0, 0, 0, 0, 0, 0, 0};

    for (int t = 0; t < T_LEN; t++) {
        const int buf = t & 1, nbuf = buf ^ 1;

        u64 ai[4], af[4], ag[4], ao[4];
#pragma unroll
        for (int sp = 0; sp < 4; sp++) {
            ai[sp] = BI; af[sp] = BF; ag[sp] = BG; ao[sp] = BO;
        }
        // hh1 first: own h1(t-1); independent of L0's h0(t).
#pragma unroll
        for (int jp = 0; jp < H_DIM / 2; jp++) {
            float4 w0 = s->whh1[2 * jp][lane];
            float4 w1 = s->whh1[2 * jp + 1][lane];
#define ACT_H1(sp) (&st->h1[buf][sp][2 * jp])
            JP_STEP(w0, w1, ACT_H1);
#undef ACT_H1
        }
        pair_bar(pair);  // wait for L0's h0(t) in h0[nbuf]
#pragma unroll
        for (int jp = 0; jp < H_DIM / 2; jp++) {
            float4 w0 = s->wih1[2 * jp][lane];
            float4 w1 = s->wih1[2 * jp + 1][lane];
#define ACT_H0N(sp) (&st->h0[nbuf][sp][2 * jp])
            JP_STEP(w0, w1, ACT_H0N);
#undef ACT_H0N
        }
        // Cell 1 + stage h1(t)
#pragma unroll
        for (int sp = 0; sp < 4; sp++) {
            float2 vi = unpack2(ai[sp]), vf = unpack2(af[sp]);
            float2 vg = unpack2(ag[sp]), vo = unpack2(ao[sp]);
            float i0 = sig_ap(vi.x), i1 = sig_ap(vi.y);
            float f0 = sig_ap(vf.x), f1 = sig_ap(vf.y);
            float g0 = tanh_ap(vg.x), g1 = tanh_ap(vg.y);
            float o0 = sig_ap(vo.x), o1 = sig_ap(vo.y);
            c1[2 * sp]     = fmaf(f0, c1[2 * sp],     i0 * g0);
            c1[2 * sp + 1] = fmaf(f1, c1[2 * sp + 1], i1 * g1);
            h1n[2 * sp]     = o0 * tanh_ap(c1[2 * sp]);
            h1n[2 * sp + 1] = o1 * tanh_ap(c1[2 * sp + 1]);
            st->h1[nbuf][sp][lane] = pack2f(h1n[2 * sp], h1n[2 * sp + 1]);
        }
        __syncwarp();  // order h1 stores vs next iteration's cross-lane reads
    }

    // ---- Head (L1 warp): z = relu(h1 @ W1.T + b1); y = z @ W2.T + b2 ----
    float bias2 = __ldg(b2);
    float bm = (lane < 16) ? __ldg(b1 + lane) : 0.f;
    float w2m = (lane < 16) ? __ldg(W2 + lane) : 0.f;
    float z[8];
#pragma unroll
    for (int ss = 0; ss < 8; ss++) z[ss] = bm;
#pragma unroll
    for (int j = 0; j < H_DIM; j++) {
        float wm = (lane < 16) ? __ldg(W1 + lane * H_DIM + j) : 0.f;
#pragma unroll
        for (int ss = 0; ss < 8; ss++) {
            float hj = __shfl_sync(FULLMASK, h1n[ss], j);
            z[ss] = fmaf(wm, hj, z[ss]);
        }
    }
#pragma unroll
    for (int ss = 0; ss < 8; ss++) {
        float v = fmaxf(z[ss], 0.f) * w2m;
#pragma unroll
        for (int off = 8; off >= 1; off >>= 1)
            v += __shfl_xor_sync(FULLMASK, v, off, 16);
        if (lane == 0) out[seq_base + ss] = v + bias2;
    }
}

extern "C" void kernel_launch(void* const* d_in, const int* in_sizes, int n_in,
                              void* d_out, int out_size) {
    const float* x    = (const float*)d_in[0];
    const float* Wih0 = (const float*)d_in[1];
    const float* Whh0 = (const float*)d_in[2];
    const float* bih0 = (const float*)d_in[3];
    const float* bhh0 = (const float*)d_in[4];
    const float* Wih1 = (const float*)d_in[5];
    const float* Whh1 = (const float*)d_in[6];
    const float* bih1 = (const float*)d_in[7];
    const float* bhh1 = (const float*)d_in[8];
    const float* W1   = (const float*)d_in[9];
    const float* b1   = (const float*)d_in[10];
    const float* W2   = (const float*)d_in[11];
    const float* b2   = (const float*)d_in[12];
    float* out = (float*)d_out;

    int batch = in_sizes[0] / (T_LEN * IN_DIM);  // 4096

    cudaFuncSetAttribute(lstm_fused_kernel,
                         cudaFuncAttributeMaxDynamicSharedMemorySize,
                         (int)sizeof(SmemAll));

    int pairs = (batch + SEQ_PER_PAIR - 1) / SEQ_PER_PAIR;          // 512
    int blocks = (pairs + PAIRS_PER_BLOCK - 1) / PAIRS_PER_BLOCK;   // 128
    lstm_fused_kernel<<<blocks, THREADS, sizeof(SmemAll)>>>(
        x, Wih0, Whh0, bih0, bhh0, Wih1, Whh1, bih1, bhh1,
        W1, b1, W2, b2, out, batch);
}

// round 15
// speedup vs baseline: 1.0395x; 1.0395x over previous
#include <cuda_runtime.h>

// 2-layer LSTM (IN=16, H=32, T=512, B=4096) + MLP head, fully fused.
// R15 = R13 (layer-split warp pairs, S=8, smem-staged seq-pair acts, HW
// tanh.approx) with PRODUCER/CONSUMER SPLIT BARRIERS:
//   A0/A1 (parity): L0 bar.arrive after publishing h0(t)  [non-blocking],
//                   L1 bar.sync before reading h0(t).
//   C:              L1 bar.sync right after its ih1 reads of h0(u)
//                   (certifies slot free), L0 bar.sync before overwriting
//                   that slot two steps later.
// L0 free-runs up to 2 steps ahead -> L1 (critical path) finds A already
// released every step; L0 blocks at C only under true back-pressure.
// Counts: A arrive/sync 512/512; C 510/510 (L1 skips last 2). Parity A-bars
// + C interlock bound outstanding arrives to 1 per phase (no aliasing).

#define FULLMASK 0xffffffffu
typedef unsigned long long u64;

constexpr int T_LEN = 512;
constexpr int IN_DIM = 16;
constexpr int H_DIM = 32;
constexpr int SEQ_PER_PAIR = 8;
constexpr int PAIRS_PER_BLOCK = 4;
constexpr int THREADS = 256;          // warps 0-3 = L0 of pair w, 4-7 = L1
constexpr int HROW = 34;              // u64 row stride (272B, 16B-aligned)
constexpr int XROW = 18;              // u64 row stride (144B, 16B-aligned)

// Weights: [j][unit] float4 = (wi,wf,wg,wo).
struct SmemW {
    float4 wih0[IN_DIM][H_DIM];
    float4 whh0[H_DIM][H_DIM];
    float4 wih1[H_DIM][H_DIM];
    float4 whh1[H_DIM][H_DIM];
    float4 bg0[H_DIM];
    float4 bg1[H_DIM];
};

// Per-pair staging. Rows: [seq-pair sp][unit/dim as u64 = (val_s0, val_s1)]
struct __align__(16) Stage {
    u64 h0[2][4][HROW];   // slot t&1 = h0(t); written by L0, read by both
    u64 h1[2][4][HROW];   // L1-private
    u64 x[2][4][XROW];    // L0-private
};

struct SmemAll {
    SmemW w;
    Stage st[PAIRS_PER_BLOCK];
};

__device__ __forceinline__ u64 fma2(u64 a, u64 b, u64 c) {
    u64 d;
    asm("fma.rn.f32x2 %0, %1, %2, %3;" : "=l"(d) : "l"(a), "l"(b), "l"(c));
    return d;
}
__device__ __forceinline__ u64 pack2(float v) {
    u64 r;
    asm("mov.b64 %0, {%1, %1};" : "=l"(r) : "f"(v));
    return r;
}
__device__ __forceinline__ u64 pack2f(float a, float b) {
    u64 r;
    asm("mov.b64 %0, {%1, %2};" : "=l"(r) : "f"(a), "f"(b));
    return r;
}
__device__ __forceinline__ float2 unpack2(u64 v) {
    float2 r;
    asm("mov.b64 {%0, %1}, %2;" : "=f"(r.x), "=f"(r.y) : "l"(v));
    return r;
}

__device__ __forceinline__ float tanh_ap(float v) {
    float r;
    asm("tanh.approx.f32 %0, %1;" : "=f"(r) : "f"(v));
    return r;
}
__device__ __forceinline__ float sig_ap(float v) {
    return fmaf(tanh_ap(v * 0.5f), 0.5f, 0.5f);
}

__device__ __forceinline__ void bar_sync64(int id) {
    asm volatile("bar.sync %0, 64;" :: "r"(id) : "memory");
}
__device__ __forceinline__ void bar_arrive64(int id) {
    asm volatile("bar.arrive %0, 64;" :: "r"(id) : "memory");
}

// One j-pair contribution: weight quads w0 (j=2jp), w1 (j=2jp+1); acts are
// seq-pair-packed u64. 8 FFMA2 per sp.
#define JP_STEP(W0, W1, ACTP)                                              \
    do {                                                                   \
        u64 wi0 = pack2((W0).x), wf0 = pack2((W0).y);                      \
        u64 wg0 = pack2((W0).z), wo0 = pack2((W0).w);                      \
        u64 wi1 = pack2((W1).x), wf1 = pack2((W1).y);                      \
        u64 wg1 = pack2((W1).z), wo1 = pack2((W1).w);                      \
        _Pragma("unroll")                                                  \
        for (int sp = 0; sp < 4; sp++) {                                   \
            ulonglong2 a = *reinterpret_cast<const ulonglong2*>(ACTP(sp)); \
            ai[sp] = fma2(wi0, a.x, ai[sp]);                               \
            af[sp] = fma2(wf0, a.x, af[sp]);                               \
            ag[sp] = fma2(wg0, a.x, ag[sp]);                               \
            ao[sp] = fma2(wo0, a.x, ao[sp]);                               \
            ai[sp] = fma2(wi1, a.y, ai[sp]);                               \
            af[sp] = fma2(wf1, a.y, af[sp]);                               \
            ag[sp] = fma2(wg1, a.y, ag[sp]);                               \
            ao[sp] = fma2(wo1, a.y, ao[sp]);                               \
        }                                                                  \
    } while (0)

__global__ void __launch_bounds__(THREADS, 1)
lstm_fused_kernel(const float* __restrict__ x,
                  const float* __restrict__ Wih0, const float* __restrict__ Whh0,
                  const float* __restrict__ bih0, const float* __restrict__ bhh0,
                  const float* __restrict__ Wih1, const float* __restrict__ Whh1,
                  const float* __restrict__ bih1, const float* __restrict__ bhh1,
                  const float* __restrict__ W1, const float* __restrict__ b1,
                  const float* __restrict__ W2, const float* __restrict__ b2,
                  float* __restrict__ out, int batch) {
    extern __shared__ char smem_raw[];
    SmemAll* sm = reinterpret_cast<SmemAll*>(smem_raw);
    SmemW* s = &sm->w;

    const int tid = threadIdx.x;

    // ---- Stage weights as [j][unit] gate quads ----
    for (int i = tid; i < IN_DIM * H_DIM; i += THREADS) {
        int j = i / H_DIM, u = i % H_DIM;
        s->wih0[j][u] = make_float4(Wih0[(0 * H_DIM + u) * IN_DIM + j],
                                    Wih0[(1 * H_DIM + u) * IN_DIM + j],
                                    Wih0[(2 * H_DIM + u) * IN_DIM + j],
                                    Wih0[(3 * H_DIM + u) * IN_DIM + j]);
    }
    for (int i = tid; i < H_DIM * H_DIM; i += THREADS) {
        int j = i / H_DIM, u = i % H_DIM;
        s->whh0[j][u] = make_float4(Whh0[(0 * H_DIM + u) * H_DIM + j],
                                    Whh0[(1 * H_DIM + u) * H_DIM + j],
                                    Whh0[(2 * H_DIM + u) * H_DIM + j],
                                    Whh0[(3 * H_DIM + u) * H_DIM + j]);
        s->wih1[j][u] = make_float4(Wih1[(0 * H_DIM + u) * H_DIM + j],
                                    Wih1[(1 * H_DIM + u) * H_DIM + j],
                                    Wih1[(2 * H_DIM + u) * H_DIM + j],
                                    Wih1[(3 * H_DIM + u) * H_DIM + j]);
        s->whh1[j][u] = make_float4(Whh1[(0 * H_DIM + u) * H_DIM + j],
                                    Whh1[(1 * H_DIM + u) * H_DIM + j],
                                    Whh1[(2 * H_DIM + u) * H_DIM + j],
                                    Whh1[(3 * H_DIM + u) * H_DIM + j]);
    }
    for (int u = tid; u < H_DIM; u += THREADS) {
        s->bg0[u] = make_float4(bih0[0 * H_DIM + u] + bhh0[0 * H_DIM + u],
                                bih0[1 * H_DIM + u] + bhh0[1 * H_DIM + u],
                                bih0[2 * H_DIM + u] + bhh0[2 * H_DIM + u],
                                bih0[3 * H_DIM + u] + bhh0[3 * H_DIM + u]);
        s->bg1[u] = make_float4(bih1[0 * H_DIM + u] + bhh1[0 * H_DIM + u],
                                bih1[1 * H_DIM + u] + bhh1[1 * H_DIM + u],
                                bih1[2 * H_DIM + u] + bhh1[2 * H_DIM + u],
                                bih1[3 * H_DIM + u] + bhh1[3 * H_DIM + u]);
    }

    const int warp = tid >> 5;
    const int lane = tid & 31;         // lane = hidden unit
    const int pair = warp & 3;
    const int role = warp >> 2;        // 0 = layer-0 warp, 1 = layer-1 warp
    Stage* st = &sm->st[pair];
    const int seq_base = (blockIdx.x * PAIRS_PER_BLOCK + pair) * SEQ_PER_PAIR;

    // Barrier ids: A0, A1 (h0-ready, by parity), C (slot-free back-pressure)
    const int BAR_A0 = 1 + pair * 3;
    const int BAR_A1 = 2 + pair * 3;
    const int BAR_C  = 3 + pair * 3;

    const int xs = lane >> 2;
    const int xq = lane & 3;
    const size_t seq_stride = (size_t)T_LEN * IN_DIM;
    const float* xload = x + (size_t)(seq_base + xs) * seq_stride + 4 * xq;

    // ---- Init staging ----
    if (seq_base < batch) {
        if (role == 0) {
            // h0(-1) lives in slot 1 ((t-1)&1 for t=0).
#pragma unroll
            for (int sp = 0; sp < 4; sp++) st->h0[1][sp][lane] = 0ull;
            float4 v = *reinterpret_cast<const float4*>(xload);
            float* fr = reinterpret_cast<float*>(st->x[0][xs >> 1]);
            int half = xs & 1;
            fr[(4 * xq + 0) * 2 + half] = v.x;
            fr[(4 * xq + 1) * 2 + half] = v.y;
            fr[(4 * xq + 2) * 2 + half] = v.z;
            fr[(4 * xq + 3) * 2 + half] = v.w;
        } else {
#pragma unroll
            for (int sp = 0; sp < 4; sp++) st->h1[0][sp][lane] = 0ull;
        }
    }
    __syncthreads();
    if (seq_base >= batch) return;

    if (role == 0) {
        // ================= Layer-0 warp (producer, runs ahead) =============
        const float4 bv = s->bg0[lane];
        const u64 BI = pack2(bv.x), BF = pack2(bv.y);
        const u64 BG = pack2(bv.z), BO = pack2(bv.w);
        float c0[8] = {0, 0, 0, 0, 0, 0, 0, 0};

        for (int t = 0; t < T_LEN; t++) {
            const int xbuf = t & 1;
            const int hprev = (t + 1) & 1;   // h0(t-1) slot
            const int hcur = t & 1;          // h0(t) slot (overwrites h0(t-2))

            if (t >= 2) bar_sync64(BAR_C);   // L1 done reading h0(t-2)

            float4 xn = make_float4(0.f, 0.f, 0.f, 0.f);
            if (t + 1 < T_LEN)
                xn = *reinterpret_cast<const float4*>(xload + (t + 1) * IN_DIM);

            u64 ai[4], af[4], ag[4], ao[4];
#pragma unroll
            for (int sp = 0; sp < 4; sp++) {
                ai[sp] = BI; af[sp] = BF; ag[sp] = BG; ao[sp] = BO;
            }
#pragma unroll
            for (int jp = 0; jp < IN_DIM / 2; jp++) {
                float4 w0 = s->wih0[2 * jp][lane];
                float4 w1 = s->wih0[2 * jp + 1][lane];
#define ACT_X(sp) (&st->x[xbuf][sp][2 * jp])
                JP_STEP(w0, w1, ACT_X);
#undef ACT_X
            }
#pragma unroll
            for (int jp = 0; jp < H_DIM / 2; jp++) {
                float4 w0 = s->whh0[2 * jp][lane];
                float4 w1 = s->whh0[2 * jp + 1][lane];
#define ACT_H0(sp) (&st->h0[hprev][sp][2 * jp])
                JP_STEP(w0, w1, ACT_H0);
#undef ACT_H0
            }
            // Cell 0 + publish h0(t)
#pragma unroll
            for (int sp = 0; sp < 4; sp++) {
                float2 vi = unpack2(ai[sp]), vf = unpack2(af[sp]);
                float2 vg = unpack2(ag[sp]), vo = unpack2(ao[sp]);
                float i0 = sig_ap(vi.x), i1 = sig_ap(vi.y);
                float f0 = sig_ap(vf.x), f1 = sig_ap(vf.y);
                float g0 = tanh_ap(vg.x), g1 = tanh_ap(vg.y);
                float o0 = sig_ap(vo.x), o1 = sig_ap(vo.y);
                c0[2 * sp]     = fmaf(f0, c0[2 * sp],     i0 * g0);
                c0[2 * sp + 1] = fmaf(f1, c0[2 * sp + 1], i1 * g1);
                st->h0[hcur][sp][lane] =
                    pack2f(o0 * tanh_ap(c0[2 * sp]),
                           o1 * tanh_ap(c0[2 * sp + 1]));
            }
            // Stage x(t+1)
            {
                float* fr = reinterpret_cast<float*>(st->x[xbuf ^ 1][xs >> 1]);
                int half = xs & 1;
                fr[(4 * xq + 0) * 2 + half] = xn.x;
                fr[(4 * xq + 1) * 2 + half] = xn.y;
                fr[(4 * xq + 2) * 2 + half] = xn.z;
                fr[(4 * xq + 3) * 2 + half] = xn.w;
            }
            __syncwarp();  // order cross-lane h0/x stores vs own next reads
            bar_arrive64((t & 1) ? BAR_A1 : BAR_A0);  // publish, NON-blocking
        }
        return;
    }

    // ================= Layer-1 warp (consumer, critical path) =============
    const float4 bv = s->bg1[lane];
    const u64 BI = pack2(bv.x), BF = pack2(bv.y);
    const u64 BG = pack2(bv.z), BO = pack2(bv.w);
    float c1[8] = {0, 0, 0, 0, 0, 0, 0, 0};
    float h1n[8] = {0, 0, 0, 0, 0, 0, 0, 0};

    for (int u = 0; u < T_LEN; u++) {
        const int h1rd = u & 1;          // h1(u-1)
        const int h1wr = h1rd ^ 1;       // h1(u)
        const int h0rd = u & 1;          // h0(u)

        u64 ai[4], af[4], ag[4], ao[4];
#pragma unroll
        for (int sp = 0; sp < 4; sp++) {
            ai[sp] = BI; af[sp] = BF; ag[sp] = BG; ao[sp] = BO;
        }
        // hh1 first: own h1(u-1); independent of h0(u).
#pragma unroll
        for (int jp = 0; jp < H_DIM / 2; jp++) {
            float4 w0 = s->whh1[2 * jp][lane];
            float4 w1 = s->whh1[2 * jp + 1][lane];
#define ACT_H1(sp) (&st->h1[h1rd][sp][2 * jp])
            JP_STEP(w0, w1, ACT_H1);
#undef ACT_H1
        }
        bar_sync64((u & 1) ? BAR_A1 : BAR_A0);  // h0(u) ready (usually free)
#pragma unroll
        for (int jp = 0; jp < H_DIM / 2; jp++) {
            float4 w0 = s->wih1[2 * jp][lane];
            float4 w1 = s->wih1[2 * jp + 1][lane];
#define ACT_H0N(sp) (&st->h0[h0rd][sp][2 * jp])
            JP_STEP(w0, w1, ACT_H0N);
#undef ACT_H0N
        }
        if (u < T_LEN - 2) bar_sync64(BAR_C);   // certify h0(u) slot free
        // Cell 1 + stage h1(u)
#pragma unroll
        for (int sp = 0; sp < 4; sp++) {
            float2 vi = unpack2(ai[sp]), vf = unpack2(af[sp]);
            float2 vg = unpack2(ag[sp]), vo = unpack2(ao[sp]);
            float i0 = sig_ap(vi.x), i1 = sig_ap(vi.y);
            float f0 = sig_ap(vf.x), f1 = sig_ap(vf.y);
            float g0 = tanh_ap(vg.x), g1 = tanh_ap(vg.y);
            float o0 = sig_ap(vo.x), o1 = sig_ap(vo.y);
            c1[2 * sp]     = fmaf(f0, c1[2 * sp],     i0 * g0);
            c1[2 * sp + 1] = fmaf(f1, c1[2 * sp + 1], i1 * g1);
            h1n[2 * sp]     = o0 * tanh_ap(c1[2 * sp]);
            h1n[2 * sp + 1] = o1 * tanh_ap(c1[2 * sp + 1]);
            st->h1[h1wr][sp][lane] = pack2f(h1n[2 * sp], h1n[2 * sp + 1]);
        }
        __syncwarp();  // order h1 stores vs next iteration's cross-lane reads
    }

    // ---- Head (L1 warp): z = relu(h1 @ W1.T + b1); y = z @ W2.T + b2 ----
    float bias2 = __ldg(b2);
    float bm = (lane < 16) ? __ldg(b1 + lane) : 0.f;
    float w2m = (lane < 16) ? __ldg(W2 + lane) : 0.f;
    float z[8];
#pragma unroll
    for (int ss = 0; ss < 8; ss++) z[ss] = bm;
#pragma unroll
    for (int j = 0; j < H_DIM; j++) {
        float wm = (lane < 16) ? __ldg(W1 + lane * H_DIM + j) : 0.f;
#pragma unroll
        for (int ss = 0; ss < 8; ss++) {
            float hj = __shfl_sync(FULLMASK, h1n[ss], j);
            z[ss] = fmaf(wm, hj, z[ss]);
        }
    }
#pragma unroll
    for (int ss = 0; ss < 8; ss++) {
        float v = fmaxf(z[ss], 0.f) * w2m;
#pragma unroll
        for (int off = 8; off >= 1; off >>= 1)
            v += __shfl_xor_sync(FULLMASK, v, off, 16);
        if (lane == 0) out[seq_base + ss] = v + bias2;
    }
}

extern "C" void kernel_launch(void* const* d_in, const int* in_sizes, int n_in,
                              void* d_out, int out_size) {
    const float* x    = (const float*)d_in[0];
    const float* Wih0 = (const float*)d_in[1];
    const float* Whh0 = (const float*)d_in[2];
    const float* bih0 = (const float*)d_in[3];
    const float* bhh0 = (const float*)d_in[4];
    const float* Wih1 = (const float*)d_in[5];
    const float* Whh1 = (const float*)d_in[6];
    const float* bih1 = (const float*)d_in[7];
    const float* bhh1 = (const float*)d_in[8];
    const float* W1   = (const float*)d_in[9];
    const float* b1   = (const float*)d_in[10];
    const float* W2   = (const float*)d_in[11];
    const float* b2   = (const float*)d_in[12];
    float* out = (float*)d_out;

    int batch = in_sizes[0] / (T_LEN * IN_DIM);  // 4096

    cudaFuncSetAttribute(lstm_fused_kernel,
                         cudaFuncAttributeMaxDynamicSharedMemorySize,
                         (int)sizeof(SmemAll));

    int pairs = (batch + SEQ_PER_PAIR - 1) / SEQ_PER_PAIR;          // 512
    int blocks = (pairs + PAIRS_PER_BLOCK - 1) / PAIRS_PER_BLOCK;   // 128
    lstm_fused_kernel<<<blocks, THREADS, sizeof(SmemAll)>>>(
        x, Wih0, Whh0, bih0, bhh0, Wih1, Whh1, bih1, bhh1,
        W1, b1, W2, b2, out, batch);
}